// round 5
// baseline (speedup 1.0000x reference)
#include <cuda_runtime.h>

// ---------------------------------------------------------------------------
// LTFGW on GB300 (sm_103a).
//   Stage 1 (k1_dots): D = X @ TF^T  [10000 x 100], xsq[n] = ||x_n||^2,
//                      gsq[tk] = ||tf_tk||^2. Two passes over tf halves so
//                      everything fits in 48KB static shared memory.
//   Stage 2 (k2_solver): one thread per (node, template) pair. Transport plan
//   (17x10) lives fully in registers; E = exp(-M) lives in shared memory.
//   Primal-domain Sinkhorn (u = p/(Kv), v = q/(K^T u)) replaces log-domain
//   logsumexp: identical math, ~20x fewer MUFU ops. Star-graph structure
//   collapses the GW cost to 2 distinct rows -> only 20 exps per outer iter.
//   R3 fix: ctqs computation is BT-strided (was guarded by tid<100 with a
//   64-thread block -> entries 64..99 uninitialized -> 6.6% rel_err).
//   R4: resubmission of R3 (round 4 bench was an infra container failure).
// ---------------------------------------------------------------------------

#define N_NODES 10000
#define DIM 128
#define DEG 16
#define M_LOC 17
#define T_TPL 10
#define K_TPL 10
#define TK 100
#define N_PAIRS (N_NODES * T_TPL)
#define N_OUTER 5
#define N_SINK 10

__device__ float g_D[N_NODES * TK];   // dot(x[n], tf[t,k])
__device__ float g_xsq[N_NODES];
__device__ float g_gsq[TK];

// ---------------- Stage 1: dots + norms ----------------
#define K1_NPB 32            // nodes per block
#define K1_HALF 50           // tf rows per pass
#define XS_STRIDE 129        // odd stride -> conflict-free cross-row access

__global__ void __launch_bounds__(128) k1_dots(const float* __restrict__ x,
                                               const float* __restrict__ tf) {
    __shared__ float tfs[DIM * K1_HALF];        // [e][tkl]   25600 B
    __shared__ float xs[K1_NPB * XS_STRIDE];    //            16512 B
    const int tid = threadIdx.x;
    const int nbase = blockIdx.x * K1_NPB;

    // cache 32 x-rows
    for (int idx = tid; idx < K1_NPB * DIM; idx += 128) {
        int nl = idx >> 7, e = idx & 127;
        int n = nbase + nl;
        xs[nl * XS_STRIDE + e] = (n < N_NODES) ? x[n * DIM + e] : 0.f;
    }

    #pragma unroll 1
    for (int s = 0; s < 2; s++) {
        __syncthreads();
        // load tf half, transposed: tfs[e*50 + tkl] = tf[s*50+tkl][e]
        for (int idx = tid; idx < K1_HALF * DIM; idx += 128) {
            int tkl = idx >> 7, e = idx & 127;
            tfs[e * K1_HALF + tkl] = tf[(s * K1_HALF + tkl) * DIM + e];
        }
        __syncthreads();

        if (s == 0 && tid >= 64 && tid < 64 + K1_NPB) {
            int nl = tid - 64;
            int n = nbase + nl;
            if (n < N_NODES) {
                float acc = 0.f;
                #pragma unroll 8
                for (int e = 0; e < DIM; e++) {
                    float c = xs[nl * XS_STRIDE + e];
                    acc += c * c;
                }
                g_xsq[n] = acc;
            }
        }
        if (blockIdx.x == 0 && tid < K1_HALF) {
            float acc = 0.f;
            #pragma unroll 8
            for (int e = 0; e < DIM; e++) {
                float c = tfs[e * K1_HALF + tid];
                acc += c * c;
            }
            g_gsq[s * K1_HALF + tid] = acc;
        }
        if (tid < K1_HALF) {
            #pragma unroll 1
            for (int nl = 0; nl < K1_NPB; nl++) {
                int n = nbase + nl;
                if (n >= N_NODES) break;
                float acc = 0.f;
                #pragma unroll 16
                for (int e = 0; e < DIM; e++)
                    acc += xs[nl * XS_STRIDE + e] * tfs[e * K1_HALF + tid];
                g_D[n * TK + s * K1_HALF + tid] = acc;
            }
        }
    }
}

// ---------------- Stage 2: FGW solver, thread per pair ----------------
#define BT 64

__global__ void __launch_bounds__(BT, 2) k2_solver(const int* __restrict__ edge_index,
                                                   const float* __restrict__ templates,
                                                   float* __restrict__ out) {
    __shared__ float Es[M_LOC * K_TPL * BT];          // 43520 B: E=exp(-M), col per thread
    __shared__ float Cts[T_TPL * K_TPL * K_TPL];      // all template adjacencies
    __shared__ float ctqs[TK];                        // (Ct^2 @ q)
    __shared__ float gsqs[TK];
    const int tid = threadIdx.x;
    const int pair = blockIdx.x * BT + tid;

    for (int idx = tid; idx < T_TPL * K_TPL * K_TPL; idx += BT) Cts[idx] = templates[idx];
    for (int idx = tid; idx < TK; idx += BT) gsqs[idx] = g_gsq[idx];
    __syncthreads();
    for (int idx = tid; idx < TK; idx += BT) {      // BT-strided (R3 fix)
        int t = idx / K_TPL, j = idx - t * K_TPL;
        float s = 0.f;
        #pragma unroll
        for (int jp = 0; jp < K_TPL; jp++) { float c = Cts[t * 100 + j * 10 + jp]; s += c * c; }
        ctqs[idx] = s * 0.1f;
    }
    __syncthreads();
    if (pair >= N_PAIRS) return;

    const int n = pair / T_TPL;
    const int t = pair - n * T_TPL;
    float* ep = Es + tid;

    // ---- E = exp(-M), M_ij = mean_d (F_i - G_j)^2 via precomputed dots ----
    {
        const float* gs = gsqs + t * K_TPL;
        #pragma unroll
        for (int k = 0; k < M_LOC; k++) {
            int r = (k == 0) ? n : edge_index[n * DEG + (k - 1)];
            float xsq = g_xsq[r];
            const float* Dp = g_D + r * TK + t * K_TPL;
            #pragma unroll
            for (int j = 0; j < K_TPL; j++) {
                float Mij = (xsq + gs[j] - 2.f * Dp[j]) * (1.f / 128.f);
                ep[(k * K_TPL + j) * BT] = __expf(-Mij);
            }
        }
    }

    const float P   = 1.f / 17.f;     // p_i
    const float P0c = 16.f / 17.f;    // (Ci^2 @ p) row 0
    const float Q   = 0.1f;           // q_j
    const float* ct = Cts + t * 100;
    const float* cq = ctqs + t * K_TPL;

    float Kr[170];                    // holds T at loop top, Gibbs kernel inside
    #pragma unroll
    for (int ij = 0; ij < 170; ij++) Kr[ij] = 1.f / 170.f;   // T0 = p q^T

    float v[10];

    #pragma unroll 1
    for (int outer = 0; outer < N_OUTER; outer++) {
        // ---- GW stats of current T: a_j = sum_{i>=1} T_ij ; row0 of T = Kr[0..9] ----
        float a[10];
        #pragma unroll
        for (int j = 0; j < 10; j++) a[j] = 0.f;
        #pragma unroll
        for (int i = 1; i < 17; i++) {
            #pragma unroll
            for (int j = 0; j < 10; j++) a[j] += Kr[i * 10 + j];
        }
        // cost (excl. M) row0: 16/17 + ctq_j - 2*(a@Ct)_j ; rows>=1: 1/17 + ctq_j - 2*(t0@Ct)_j
        float w[10], w0[10];
        #pragma unroll
        for (int j = 0; j < 10; j++) {
            float b = 0.f, G0 = 0.f;
            #pragma unroll
            for (int jp = 0; jp < 10; jp++) {
                float c = ct[j * 10 + jp];     // Ct symmetric
                b  += Kr[jp] * c;
                G0 += a[jp] * c;
            }
            float c2 = cq[j];
            w[j]  = __expf(-2.f * (P   + c2 - 2.f * b));    // /EPS = *2
            w0[j] = __expf(-2.f * (P0c + c2 - 2.f * G0));
        }
        // ---- Gibbs kernel: K = T * exp(-M) * w ----
        #pragma unroll
        for (int i = 0; i < 17; i++) {
            #pragma unroll
            for (int j = 0; j < 10; j++)
                Kr[i * 10 + j] *= ep[(i * 10 + j) * BT] * (i == 0 ? w0[j] : w[j]);
        }
        // ---- Sinkhorn (primal domain), v starts at 1 (f=g=0) ----
        #pragma unroll
        for (int j = 0; j < 10; j++) v[j] = 1.f;
        #pragma unroll 1
        for (int it = 0; it < N_SINK - 1; it++) {
            float s[10];
            #pragma unroll
            for (int j = 0; j < 10; j++) s[j] = 0.f;
            #pragma unroll
            for (int i = 0; i < 17; i++) {
                float kv = 0.f;
                #pragma unroll
                for (int j = 0; j < 10; j++) kv += Kr[i * 10 + j] * v[j];
                float u = __fdividef(P, kv);
                #pragma unroll
                for (int j = 0; j < 10; j++) s[j] += Kr[i * 10 + j] * u;
            }
            #pragma unroll
            for (int j = 0; j < 10; j++) v[j] = __fdividef(Q, s[j]);
        }
        // last Sinkhorn iter keeps u (f10 pairs with g10 in the reference scan),
        // then fold: T = K o u v^T
        {
            float s[10], u[17];
            #pragma unroll
            for (int j = 0; j < 10; j++) s[j] = 0.f;
            #pragma unroll
            for (int i = 0; i < 17; i++) {
                float kv = 0.f;
                #pragma unroll
                for (int j = 0; j < 10; j++) kv += Kr[i * 10 + j] * v[j];
                u[i] = __fdividef(P, kv);
                #pragma unroll
                for (int j = 0; j < 10; j++) s[j] += Kr[i * 10 + j] * u[i];
            }
            #pragma unroll
            for (int j = 0; j < 10; j++) v[j] = __fdividef(Q, s[j]);
            #pragma unroll
            for (int i = 0; i < 17; i++) {
                #pragma unroll
                for (int j = 0; j < 10; j++) Kr[i * 10 + j] *= u[i] * v[j];
            }
        }
    }

    // ---- objective: sum T_ij * (0.5*M_ij + 0.5*(constC_ij - 2*G_ij)) ----
    float a[10];
    #pragma unroll
    for (int j = 0; j < 10; j++) a[j] = 0.f;
    #pragma unroll
    for (int i = 1; i < 17; i++) {
        #pragma unroll
        for (int j = 0; j < 10; j++) a[j] += Kr[i * 10 + j];
    }
    float obj = 0.f;
    #pragma unroll
    for (int j = 0; j < 10; j++) {
        float b = 0.f, G0 = 0.f;
        #pragma unroll
        for (int jp = 0; jp < 10; jp++) {
            float c = ct[j * 10 + jp];
            b  += Kr[jp] * c;
            G0 += a[jp] * c;
        }
        float c2 = cq[j];
        float M0 = -__logf(ep[j * BT]);
        obj += Kr[j] * (0.5f * M0 + 0.5f * (P0c + c2 - 2.f * G0));
        float cc = 0.5f * (P + c2 - 2.f * b);
        #pragma unroll
        for (int i = 1; i < 17; i++) {
            float Mij = -__logf(ep[(i * 10 + j) * BT]);
            obj += Kr[i * 10 + j] * (0.5f * Mij + cc);
        }
    }
    out[pair] = obj;
}

// ---------------- launch: kernel launches ONLY ----------------
extern "C" void kernel_launch(void* const* d_in, const int* in_sizes, int n_in,
                              void* d_out, int out_size) {
    const float* x    = (const float*)d_in[0];
    const int*   ei   = (const int*)d_in[1];     // row 0 = src
    const float* tmpl = (const float*)d_in[2];
    const float* tf   = (const float*)d_in[3];
    float* out = (float*)d_out;

    k1_dots<<<(N_NODES + K1_NPB - 1) / K1_NPB, 128>>>(x, tf);
    k2_solver<<<(N_PAIRS + BT - 1) / BT, BT>>>(ei, tmpl, out);
}

// round 6
// speedup vs baseline: 1.0245x; 1.0245x over previous
#include <cuda_runtime.h>

// ---------------------------------------------------------------------------
// LTFGW on GB300 (sm_103a).
//   Stage 1 (k1_dots): D = X @ TF^T, xsq, gsq (unchanged from R4).
//   Stage 2 (k2_solver): R5 = TWO LANES PER PAIR. Lane parity r owns 8 plan
//   rows (r=0: rows 1-8, r=1: rows 9-16); row 0 replicated in both lanes
//   (identical arithmetic -> exact). Column reductions close over the pair
//   with one shfl_xor(.,1). Plan registers per thread: 170 -> 90, reg cap 128
//   -> 16 warps/SM (was 8 at 255 regs), attacking the issue=37% latency bound.
//   Es uses stride-65 so paired lanes (rows differing by 80 == 16 mod 32)
//   hit disjoint bank halves -> conflict-free LDS.
// ---------------------------------------------------------------------------

#define N_NODES 10000
#define DIM 128
#define DEG 16
#define M_LOC 17
#define T_TPL 10
#define K_TPL 10
#define TK 100
#define N_PAIRS (N_NODES * T_TPL)
#define N_OUTER 5
#define N_SINK 10

__device__ float g_D[N_NODES * TK];   // dot(x[n], tf[t,k])
__device__ float g_xsq[N_NODES];
__device__ float g_gsq[TK];

// ---------------- Stage 1: dots + norms (unchanged) ----------------
#define K1_NPB 32
#define K1_HALF 50
#define XS_STRIDE 129

__global__ void __launch_bounds__(128) k1_dots(const float* __restrict__ x,
                                               const float* __restrict__ tf) {
    __shared__ float tfs[DIM * K1_HALF];
    __shared__ float xs[K1_NPB * XS_STRIDE];
    const int tid = threadIdx.x;
    const int nbase = blockIdx.x * K1_NPB;

    for (int idx = tid; idx < K1_NPB * DIM; idx += 128) {
        int nl = idx >> 7, e = idx & 127;
        int n = nbase + nl;
        xs[nl * XS_STRIDE + e] = (n < N_NODES) ? x[n * DIM + e] : 0.f;
    }

    #pragma unroll 1
    for (int s = 0; s < 2; s++) {
        __syncthreads();
        for (int idx = tid; idx < K1_HALF * DIM; idx += 128) {
            int tkl = idx >> 7, e = idx & 127;
            tfs[e * K1_HALF + tkl] = tf[(s * K1_HALF + tkl) * DIM + e];
        }
        __syncthreads();

        if (s == 0 && tid >= 64 && tid < 64 + K1_NPB) {
            int nl = tid - 64;
            int n = nbase + nl;
            if (n < N_NODES) {
                float acc = 0.f;
                #pragma unroll 8
                for (int e = 0; e < DIM; e++) {
                    float c = xs[nl * XS_STRIDE + e];
                    acc += c * c;
                }
                g_xsq[n] = acc;
            }
        }
        if (blockIdx.x == 0 && tid < K1_HALF) {
            float acc = 0.f;
            #pragma unroll 8
            for (int e = 0; e < DIM; e++) {
                float c = tfs[e * K1_HALF + tid];
                acc += c * c;
            }
            g_gsq[s * K1_HALF + tid] = acc;
        }
        if (tid < K1_HALF) {
            #pragma unroll 1
            for (int nl = 0; nl < K1_NPB; nl++) {
                int n = nbase + nl;
                if (n >= N_NODES) break;
                float acc = 0.f;
                #pragma unroll 16
                for (int e = 0; e < DIM; e++)
                    acc += xs[nl * XS_STRIDE + e] * tfs[e * K1_HALF + tid];
                g_D[n * TK + s * K1_HALF + tid] = acc;
            }
        }
    }
}

// ---------------- Stage 2: FGW solver, 2 lanes per pair ----------------
#define BT 128                 // threads per block
#define PPB 64                 // pairs per block
#define ES_STRIDE 65           // bank-skewed stride for Es

__global__ void __launch_bounds__(BT, 4) k2_solver(const int* __restrict__ edge_index,
                                                   const float* __restrict__ templates,
                                                   float* __restrict__ out) {
    __shared__ float Es[M_LOC * K_TPL * ES_STRIDE];   // 44200 B, idx (row*10+j)*65 + pairlo
    __shared__ float Cts[T_TPL * K_TPL * K_TPL];
    __shared__ float ctqs[TK];
    __shared__ float gsqs[TK];
    const int tid = threadIdx.x;
    const int r = tid & 1;                 // lane parity within pair
    const int pairlo = tid >> 1;           // pair index within block (0..63)
    const int pair = blockIdx.x * PPB + pairlo;

    for (int idx = tid; idx < T_TPL * K_TPL * K_TPL; idx += BT) Cts[idx] = templates[idx];
    for (int idx = tid; idx < TK; idx += BT) gsqs[idx] = g_gsq[idx];
    __syncthreads();
    for (int idx = tid; idx < TK; idx += BT) {
        int t = idx / K_TPL, j = idx - t * K_TPL;
        float s = 0.f;
        #pragma unroll
        for (int jp = 0; jp < K_TPL; jp++) { float c = Cts[t * 100 + j * 10 + jp]; s += c * c; }
        ctqs[idx] = s * 0.1f;
    }
    __syncthreads();
    if (pair >= N_PAIRS) return;           // warp-uniform (validity boundary is warp-aligned)

    const int n = pair / T_TPL;
    const int t = pair - n * T_TPL;
    const int base = 1 + 8 * r;            // first owned row: 1 or 9

    float* ep0 = Es + pairlo;                              // row 0, index j*65
    float* epo = Es + (base * 10) * ES_STRIDE + pairlo;    // own rows, (k*10+j)*65

    // ---- E = exp(-M) fill: 8 own rows per lane; lane0 also fills row 0 ----
    {
        const float* gs = gsqs + t * K_TPL;
        #pragma unroll
        for (int k = 0; k < 8; k++) {
            int rr = edge_index[n * DEG + (base - 1 + k)];
            float xsq = g_xsq[rr];
            const float* Dp = g_D + rr * TK + t * K_TPL;
            #pragma unroll
            for (int j = 0; j < 10; j++) {
                float Mij = (xsq + gs[j] - 2.f * Dp[j]) * (1.f / 128.f);
                epo[(k * 10 + j) * ES_STRIDE] = __expf(-Mij);
            }
        }
        if (r == 0) {
            float xsq = g_xsq[n];
            const float* Dp = g_D + n * TK + t * K_TPL;
            #pragma unroll
            for (int j = 0; j < 10; j++) {
                float Mij = (xsq + gs[j] - 2.f * Dp[j]) * (1.f / 128.f);
                ep0[j * ES_STRIDE] = __expf(-Mij);
            }
        }
    }
    __syncwarp();   // partner lane reads row 0 / own rows written above

    const float P   = 1.f / 17.f;
    const float P0c = 16.f / 17.f;
    const float Q   = 0.1f;
    const float* ct = Cts + t * 100;
    const float* cq = ctqs + t * K_TPL;

    float Kr0[10];                 // row 0 of plan, replicated both lanes
    float Kr[80];                  // 8 owned rows
    #pragma unroll
    for (int j = 0; j < 10; j++) Kr0[j] = 1.f / 170.f;
    #pragma unroll
    for (int ij = 0; ij < 80; ij++) Kr[ij] = 1.f / 170.f;

    float v[10];

    #pragma unroll 1
    for (int outer = 0; outer < N_OUTER; outer++) {
        // ---- a_j = colsum of rows 1..16 (own partial + partner via shfl) ----
        float a[10];
        #pragma unroll
        for (int j = 0; j < 10; j++) {
            float s = 0.f;
            #pragma unroll
            for (int k = 0; k < 8; k++) s += Kr[k * 10 + j];
            a[j] = s + __shfl_xor_sync(0xffffffffu, s, 1);
        }
        // ---- Gibbs weights: w (rows>=1, uses t0=Kr0), w0 (row 0, uses a) ----
        float w[10], w0[10];
        #pragma unroll
        for (int j = 0; j < 10; j++) {
            float b = 0.f, G0 = 0.f;
            #pragma unroll
            for (int jp = 0; jp < 10; jp++) {
                float c = ct[j * 10 + jp];     // Ct symmetric
                b  += Kr0[jp] * c;
                G0 += a[jp] * c;
            }
            float c2 = cq[j];
            w[j]  = __expf(-2.f * (P   + c2 - 2.f * b));
            w0[j] = __expf(-2.f * (P0c + c2 - 2.f * G0));
        }
        // ---- Gibbs kernel: K = T * E * w ----
        #pragma unroll
        for (int j = 0; j < 10; j++) Kr0[j] *= ep0[j * ES_STRIDE] * w0[j];
        #pragma unroll
        for (int k = 0; k < 8; k++) {
            #pragma unroll
            for (int j = 0; j < 10; j++)
                Kr[k * 10 + j] *= epo[(k * 10 + j) * ES_STRIDE] * w[j];
        }
        // ---- Sinkhorn (primal), v starts at 1 ----
        #pragma unroll
        for (int j = 0; j < 10; j++) v[j] = 1.f;
        #pragma unroll 1
        for (int it = 0; it < N_SINK - 1; it++) {
            float s[10];
            float kv0 = 0.f;
            #pragma unroll
            for (int j = 0; j < 10; j++) kv0 += Kr0[j] * v[j];
            float u0h = 0.5f * __fdividef(P, kv0);          // half: counted in both lanes
            #pragma unroll
            for (int j = 0; j < 10; j++) s[j] = Kr0[j] * u0h;
            #pragma unroll
            for (int k = 0; k < 8; k++) {
                float kv = 0.f;
                #pragma unroll
                for (int j = 0; j < 10; j++) kv += Kr[k * 10 + j] * v[j];
                float u = __fdividef(P, kv);
                #pragma unroll
                for (int j = 0; j < 10; j++) s[j] += Kr[k * 10 + j] * u;
            }
            #pragma unroll
            for (int j = 0; j < 10; j++) {
                float st = s[j] + __shfl_xor_sync(0xffffffffu, s[j], 1);
                v[j] = __fdividef(Q, st);
            }
        }
        // ---- last Sinkhorn iter: keep u's, compute final v, fold T = K o u v^T ----
        {
            float s[10], uo[8];
            float kv0 = 0.f;
            #pragma unroll
            for (int j = 0; j < 10; j++) kv0 += Kr0[j] * v[j];
            float u0 = __fdividef(P, kv0);
            float u0h = 0.5f * u0;
            #pragma unroll
            for (int j = 0; j < 10; j++) s[j] = Kr0[j] * u0h;
            #pragma unroll
            for (int k = 0; k < 8; k++) {
                float kv = 0.f;
                #pragma unroll
                for (int j = 0; j < 10; j++) kv += Kr[k * 10 + j] * v[j];
                uo[k] = __fdividef(P, kv);
                #pragma unroll
                for (int j = 0; j < 10; j++) s[j] += Kr[k * 10 + j] * uo[k];
            }
            #pragma unroll
            for (int j = 0; j < 10; j++) {
                float st = s[j] + __shfl_xor_sync(0xffffffffu, s[j], 1);
                v[j] = __fdividef(Q, st);
            }
            #pragma unroll
            for (int j = 0; j < 10; j++) Kr0[j] *= u0 * v[j];
            #pragma unroll
            for (int k = 0; k < 8; k++) {
                #pragma unroll
                for (int j = 0; j < 10; j++) Kr[k * 10 + j] *= uo[k] * v[j];
            }
        }
    }

    // ---- objective: sum T_ij * (0.5*M_ij + 0.5*(constC_ij - 2*G_ij)) ----
    float a[10];
    #pragma unroll
    for (int j = 0; j < 10; j++) {
        float s = 0.f;
        #pragma unroll
        for (int k = 0; k < 8; k++) s += Kr[k * 10 + j];
        a[j] = s + __shfl_xor_sync(0xffffffffu, s, 1);
    }
    float obj = 0.f;
    #pragma unroll
    for (int j = 0; j < 10; j++) {
        float b = 0.f, G0 = 0.f;
        #pragma unroll
        for (int jp = 0; jp < 10; jp++) {
            float c = ct[j * 10 + jp];
            b  += Kr0[jp] * c;
            G0 += a[jp] * c;
        }
        float c2 = cq[j];
        float M0 = -__logf(ep0[j * ES_STRIDE]);
        // row 0 term counted half in each lane (identical -> sums exactly)
        obj += 0.5f * Kr0[j] * (0.5f * M0 + 0.5f * (P0c + c2 - 2.f * G0));
        float cc = 0.5f * (P + c2 - 2.f * b);
        #pragma unroll
        for (int k = 0; k < 8; k++) {
            float Mij = -__logf(epo[(k * 10 + j) * ES_STRIDE]);
            obj += Kr[k * 10 + j] * (0.5f * Mij + cc);
        }
    }
    obj += __shfl_xor_sync(0xffffffffu, obj, 1);
    if (r == 0) out[pair] = obj;
}

// ---------------- launch: kernel launches ONLY ----------------
extern "C" void kernel_launch(void* const* d_in, const int* in_sizes, int n_in,
                              void* d_out, int out_size) {
    const float* x    = (const float*)d_in[0];
    const int*   ei   = (const int*)d_in[1];     // row 0 = src
    const float* tmpl = (const float*)d_in[2];
    const float* tf   = (const float*)d_in[3];
    float* out = (float*)d_out;

    k1_dots<<<(N_NODES + K1_NPB - 1) / K1_NPB, 128>>>(x, tf);
    k2_solver<<<(N_PAIRS + PPB - 1) / PPB, BT>>>(ei, tmpl, out);
}

// round 7
// speedup vs baseline: 1.1048x; 1.0784x over previous
#include <cuda_runtime.h>

// ---------------------------------------------------------------------------
// LTFGW on GB300 (sm_103a).
//   Stage 1 (k1_dots): D = X @ TF^T, xsq, gsq (unchanged).
//   Stage 2 (k2_solver): two lanes per pair; lane parity r owns 8 plan rows,
//   row 0 replicated in both lanes (exact); column reductions close with one
//   shfl_xor. R6: __launch_bounds__(128,3) -> 170 regs/thread. R5's 128-reg
//   cap spilled ~20-30 values into local memory (ncu: DRAM 36.5%, L1 55.5%
//   on an L2-resident problem); at 170 regs the ~150 live values fit and the
//   kernel returns to pure-compute behavior at 12 warps/SM.
// ---------------------------------------------------------------------------

#define N_NODES 10000
#define DIM 128
#define DEG 16
#define M_LOC 17
#define T_TPL 10
#define K_TPL 10
#define TK 100
#define N_PAIRS (N_NODES * T_TPL)
#define N_OUTER 5
#define N_SINK 10

__device__ float g_D[N_NODES * TK];   // dot(x[n], tf[t,k])
__device__ float g_xsq[N_NODES];
__device__ float g_gsq[TK];

// ---------------- Stage 1: dots + norms (unchanged) ----------------
#define K1_NPB 32
#define K1_HALF 50
#define XS_STRIDE 129

__global__ void __launch_bounds__(128) k1_dots(const float* __restrict__ x,
                                               const float* __restrict__ tf) {
    __shared__ float tfs[DIM * K1_HALF];
    __shared__ float xs[K1_NPB * XS_STRIDE];
    const int tid = threadIdx.x;
    const int nbase = blockIdx.x * K1_NPB;

    for (int idx = tid; idx < K1_NPB * DIM; idx += 128) {
        int nl = idx >> 7, e = idx & 127;
        int n = nbase + nl;
        xs[nl * XS_STRIDE + e] = (n < N_NODES) ? x[n * DIM + e] : 0.f;
    }

    #pragma unroll 1
    for (int s = 0; s < 2; s++) {
        __syncthreads();
        for (int idx = tid; idx < K1_HALF * DIM; idx += 128) {
            int tkl = idx >> 7, e = idx & 127;
            tfs[e * K1_HALF + tkl] = tf[(s * K1_HALF + tkl) * DIM + e];
        }
        __syncthreads();

        if (s == 0 && tid >= 64 && tid < 64 + K1_NPB) {
            int nl = tid - 64;
            int n = nbase + nl;
            if (n < N_NODES) {
                float acc = 0.f;
                #pragma unroll 8
                for (int e = 0; e < DIM; e++) {
                    float c = xs[nl * XS_STRIDE + e];
                    acc += c * c;
                }
                g_xsq[n] = acc;
            }
        }
        if (blockIdx.x == 0 && tid < K1_HALF) {
            float acc = 0.f;
            #pragma unroll 8
            for (int e = 0; e < DIM; e++) {
                float c = tfs[e * K1_HALF + tid];
                acc += c * c;
            }
            g_gsq[s * K1_HALF + tid] = acc;
        }
        if (tid < K1_HALF) {
            #pragma unroll 1
            for (int nl = 0; nl < K1_NPB; nl++) {
                int n = nbase + nl;
                if (n >= N_NODES) break;
                float acc = 0.f;
                #pragma unroll 16
                for (int e = 0; e < DIM; e++)
                    acc += xs[nl * XS_STRIDE + e] * tfs[e * K1_HALF + tid];
                g_D[n * TK + s * K1_HALF + tid] = acc;
            }
        }
    }
}

// ---------------- Stage 2: FGW solver, 2 lanes per pair ----------------
#define BT 128                 // threads per block
#define PPB 64                 // pairs per block
#define ES_STRIDE 65           // bank-skewed stride for Es

__global__ void __launch_bounds__(BT, 3) k2_solver(const int* __restrict__ edge_index,
                                                   const float* __restrict__ templates,
                                                   float* __restrict__ out) {
    __shared__ float Es[M_LOC * K_TPL * ES_STRIDE];   // 44200 B, idx (row*10+j)*65 + pairlo
    __shared__ float Cts[T_TPL * K_TPL * K_TPL];
    __shared__ float ctqs[TK];
    __shared__ float gsqs[TK];
    const int tid = threadIdx.x;
    const int r = tid & 1;                 // lane parity within pair
    const int pairlo = tid >> 1;           // pair index within block (0..63)
    const int pair = blockIdx.x * PPB + pairlo;

    for (int idx = tid; idx < T_TPL * K_TPL * K_TPL; idx += BT) Cts[idx] = templates[idx];
    for (int idx = tid; idx < TK; idx += BT) gsqs[idx] = g_gsq[idx];
    __syncthreads();
    for (int idx = tid; idx < TK; idx += BT) {
        int t = idx / K_TPL, j = idx - t * K_TPL;
        float s = 0.f;
        #pragma unroll
        for (int jp = 0; jp < K_TPL; jp++) { float c = Cts[t * 100 + j * 10 + jp]; s += c * c; }
        ctqs[idx] = s * 0.1f;
    }
    __syncthreads();
    if (pair >= N_PAIRS) return;           // warp-uniform (validity boundary is warp-aligned)

    const int n = pair / T_TPL;
    const int t = pair - n * T_TPL;
    const int base = 1 + 8 * r;            // first owned row: 1 or 9

    float* ep0 = Es + pairlo;                              // row 0, index j*65
    float* epo = Es + (base * 10) * ES_STRIDE + pairlo;    // own rows, (k*10+j)*65

    // ---- E = exp(-M) fill: 8 own rows per lane; lane0 also fills row 0 ----
    {
        const float* gs = gsqs + t * K_TPL;
        #pragma unroll
        for (int k = 0; k < 8; k++) {
            int rr = edge_index[n * DEG + (base - 1 + k)];
            float xsq = g_xsq[rr];
            const float* Dp = g_D + rr * TK + t * K_TPL;
            #pragma unroll
            for (int j = 0; j < 10; j++) {
                float Mij = (xsq + gs[j] - 2.f * Dp[j]) * (1.f / 128.f);
                epo[(k * 10 + j) * ES_STRIDE] = __expf(-Mij);
            }
        }
        if (r == 0) {
            float xsq = g_xsq[n];
            const float* Dp = g_D + n * TK + t * K_TPL;
            #pragma unroll
            for (int j = 0; j < 10; j++) {
                float Mij = (xsq + gs[j] - 2.f * Dp[j]) * (1.f / 128.f);
                ep0[j * ES_STRIDE] = __expf(-Mij);
            }
        }
    }
    __syncwarp();   // partner lane reads row 0 / own rows written above

    const float P   = 1.f / 17.f;
    const float P0c = 16.f / 17.f;
    const float Q   = 0.1f;
    const float* ct = Cts + t * 100;
    const float* cq = ctqs + t * K_TPL;

    float Kr0[10];                 // row 0 of plan, replicated both lanes
    float Kr[80];                  // 8 owned rows
    #pragma unroll
    for (int j = 0; j < 10; j++) Kr0[j] = 1.f / 170.f;
    #pragma unroll
    for (int ij = 0; ij < 80; ij++) Kr[ij] = 1.f / 170.f;

    float v[10];

    #pragma unroll 1
    for (int outer = 0; outer < N_OUTER; outer++) {
        // ---- a_j = colsum of rows 1..16 (own partial + partner via shfl) ----
        float a[10];
        #pragma unroll
        for (int j = 0; j < 10; j++) {
            float s = 0.f;
            #pragma unroll
            for (int k = 0; k < 8; k++) s += Kr[k * 10 + j];
            a[j] = s + __shfl_xor_sync(0xffffffffu, s, 1);
        }
        // ---- Gibbs weights: w (rows>=1, uses t0=Kr0), w0 (row 0, uses a) ----
        float w[10], w0[10];
        #pragma unroll
        for (int j = 0; j < 10; j++) {
            float b = 0.f, G0 = 0.f;
            #pragma unroll
            for (int jp = 0; jp < 10; jp++) {
                float c = ct[j * 10 + jp];     // Ct symmetric
                b  += Kr0[jp] * c;
                G0 += a[jp] * c;
            }
            float c2 = cq[j];
            w[j]  = __expf(-2.f * (P   + c2 - 2.f * b));
            w0[j] = __expf(-2.f * (P0c + c2 - 2.f * G0));
        }
        // ---- Gibbs kernel: K = T * E * w ----
        #pragma unroll
        for (int j = 0; j < 10; j++) Kr0[j] *= ep0[j * ES_STRIDE] * w0[j];
        #pragma unroll
        for (int k = 0; k < 8; k++) {
            #pragma unroll
            for (int j = 0; j < 10; j++)
                Kr[k * 10 + j] *= epo[(k * 10 + j) * ES_STRIDE] * w[j];
        }
        // ---- Sinkhorn (primal), v starts at 1 ----
        #pragma unroll
        for (int j = 0; j < 10; j++) v[j] = 1.f;
        #pragma unroll 1
        for (int it = 0; it < N_SINK - 1; it++) {
            float s[10];
            float kv0 = 0.f;
            #pragma unroll
            for (int j = 0; j < 10; j++) kv0 += Kr0[j] * v[j];
            float u0h = 0.5f * __fdividef(P, kv0);          // half: counted in both lanes
            #pragma unroll
            for (int j = 0; j < 10; j++) s[j] = Kr0[j] * u0h;
            #pragma unroll
            for (int k = 0; k < 8; k++) {
                float kv = 0.f;
                #pragma unroll
                for (int j = 0; j < 10; j++) kv += Kr[k * 10 + j] * v[j];
                float u = __fdividef(P, kv);
                #pragma unroll
                for (int j = 0; j < 10; j++) s[j] += Kr[k * 10 + j] * u;
            }
            #pragma unroll
            for (int j = 0; j < 10; j++) {
                float st = s[j] + __shfl_xor_sync(0xffffffffu, s[j], 1);
                v[j] = __fdividef(Q, st);
            }
        }
        // ---- last Sinkhorn iter: keep u's, compute final v, fold T = K o u v^T ----
        {
            float s[10], uo[8];
            float kv0 = 0.f;
            #pragma unroll
            for (int j = 0; j < 10; j++) kv0 += Kr0[j] * v[j];
            float u0 = __fdividef(P, kv0);
            float u0h = 0.5f * u0;
            #pragma unroll
            for (int j = 0; j < 10; j++) s[j] = Kr0[j] * u0h;
            #pragma unroll
            for (int k = 0; k < 8; k++) {
                float kv = 0.f;
                #pragma unroll
                for (int j = 0; j < 10; j++) kv += Kr[k * 10 + j] * v[j];
                uo[k] = __fdividef(P, kv);
                #pragma unroll
                for (int j = 0; j < 10; j++) s[j] += Kr[k * 10 + j] * uo[k];
            }
            #pragma unroll
            for (int j = 0; j < 10; j++) {
                float st = s[j] + __shfl_xor_sync(0xffffffffu, s[j], 1);
                v[j] = __fdividef(Q, st);
            }
            #pragma unroll
            for (int j = 0; j < 10; j++) Kr0[j] *= u0 * v[j];
            #pragma unroll
            for (int k = 0; k < 8; k++) {
                #pragma unroll
                for (int j = 0; j < 10; j++) Kr[k * 10 + j] *= uo[k] * v[j];
            }
        }
    }

    // ---- objective: sum T_ij * (0.5*M_ij + 0.5*(constC_ij - 2*G_ij)) ----
    float a[10];
    #pragma unroll
    for (int j = 0; j < 10; j++) {
        float s = 0.f;
        #pragma unroll
        for (int k = 0; k < 8; k++) s += Kr[k * 10 + j];
        a[j] = s + __shfl_xor_sync(0xffffffffu, s, 1);
    }
    float obj = 0.f;
    #pragma unroll
    for (int j = 0; j < 10; j++) {
        float b = 0.f, G0 = 0.f;
        #pragma unroll
        for (int jp = 0; jp < 10; jp++) {
            float c = ct[j * 10 + jp];
            b  += Kr0[jp] * c;
            G0 += a[jp] * c;
        }
        float c2 = cq[j];
        float M0 = -__logf(ep0[j * ES_STRIDE]);
        // row 0 term counted half in each lane (identical -> sums exactly)
        obj += 0.5f * Kr0[j] * (0.5f * M0 + 0.5f * (P0c + c2 - 2.f * G0));
        float cc = 0.5f * (P + c2 - 2.f * b);
        #pragma unroll
        for (int k = 0; k < 8; k++) {
            float Mij = -__logf(epo[(k * 10 + j) * ES_STRIDE]);
            obj += Kr[k * 10 + j] * (0.5f * Mij + cc);
        }
    }
    obj += __shfl_xor_sync(0xffffffffu, obj, 1);
    if (r == 0) out[pair] = obj;
}

// ---------------- launch: kernel launches ONLY ----------------
extern "C" void kernel_launch(void* const* d_in, const int* in_sizes, int n_in,
                              void* d_out, int out_size) {
    const float* x    = (const float*)d_in[0];
    const int*   ei   = (const int*)d_in[1];     // row 0 = src
    const float* tmpl = (const float*)d_in[2];
    const float* tf   = (const float*)d_in[3];
    float* out = (float*)d_out;

    k1_dots<<<(N_NODES + K1_NPB - 1) / K1_NPB, 128>>>(x, tf);
    k2_solver<<<(N_PAIRS + PPB - 1) / PPB, BT>>>(ei, tmpl, out);
}